// round 2
// baseline (speedup 1.0000x reference)
#include <cuda_runtime.h>
#include <math.h>

// ---------------------------------------------------------------------------
// Decoder_29678224015654: MusicVAE-style hierarchical LSTM decoder.
// SEQ=32, SUB=16, U=2, B=512, V=258, Z=512, CH=1024, CO=512, DH=1024.
//
//  1. h1c = tanh(z @ ci_W + ci_b)
//  2. cpre = conductor_input @ cW1i  (same every conductor step)
//  3. conductor: 2 steps x 2 LSTM layers (B=512)
//  4. c = ch @ co_W + co_b ; decoder h1_0 = tanh(c @ di_W + di_b)
//  5. dec_in pack (teacher forcing) -> one big GEMM dpre = dec_in @ dW1i
//  6. decoder recurrence: 16 steps, both segments batched (rows = 1024)
//  7. logits = hs @ fc_W + fc_b ; log_softmax ; permuted store to out
// ---------------------------------------------------------------------------

// ------------------------ scratch layout (floats) --------------------------
static constexpr size_t OFF_H1C   = 0;                                   // 512*1024
static constexpr size_t OFF_C1C   = OFF_H1C   + (size_t)512*1024;
static constexpr size_t OFF_H2C   = OFF_C1C   + (size_t)512*1024;
static constexpr size_t OFF_C2C   = OFF_H2C   + (size_t)512*1024;
static constexpr size_t OFF_CPRE  = OFF_C2C   + (size_t)512*1024;        // 512*4096
static constexpr size_t OFF_CH    = OFF_CPRE  + (size_t)512*4096;        // 2*512*1024
static constexpr size_t OFF_CVEC  = OFF_CH    + (size_t)2*512*1024;      // 1024*512
static constexpr size_t OFF_H1    = OFF_CVEC  + (size_t)1024*512;        // 1024*1024
static constexpr size_t OFF_C1    = OFF_H1    + (size_t)1024*1024;
static constexpr size_t OFF_H2    = OFF_C1    + (size_t)1024*1024;
static constexpr size_t OFF_C2    = OFF_H2    + (size_t)1024*1024;
static constexpr size_t OFF_T1    = OFF_C2    + (size_t)1024*1024;       // 1024*4096
static constexpr size_t OFF_T2    = OFF_T1    + (size_t)1024*4096;       // 1024*4096
static constexpr size_t OFF_DECIN = OFF_T2    + (size_t)1024*4096;       // 16384*770
static constexpr size_t OFF_DPRE  = OFF_DECIN + (size_t)16384*770;       // 16384*4096
static constexpr size_t OFF_HS    = OFF_DPRE  + (size_t)16384*4096;      // 16384*1024
static constexpr size_t OFF_LOG   = OFF_HS    + (size_t)16384*1024;      // 16384*258
static constexpr size_t SCRATCH_TOTAL = OFF_LOG + (size_t)16384*258;

__device__ float g_scratch[SCRATCH_TOTAL];

__device__ __forceinline__ float sigm(float x) { return 1.f / (1.f + expf(-x)); }

// ------------------------ generic SGEMM -----------------------------------
// C[M,N] = act( A@B (+ A2@B2) + bias[N]? + Cadd[M,N]? ), act: 0=none 1=tanh
// 128x128 tile, BK=16, 256 threads, 8x8 per thread.
__global__ __launch_bounds__(256, 2)
void sgemm_kernel(int M, int N, int K,
                  const float* __restrict__ A,
                  const float* __restrict__ B,
                  const float* __restrict__ A2,
                  const float* __restrict__ B2,
                  int K2,
                  const float* __restrict__ bias,
                  const float* __restrict__ Cadd,
                  float* __restrict__ C,
                  int act)
{
    __shared__ __align__(16) float As[16][132];
    __shared__ __align__(16) float Bs[16][128];

    const int tid  = threadIdx.x;
    const int tcol = tid & 15;   // N direction (x8)
    const int trow = tid >> 4;   // M direction (x8)
    const int rowBase = blockIdx.y * 128;
    const int colBase = blockIdx.x * 128;

    float acc[8][8];
#pragma unroll
    for (int i = 0; i < 8; i++)
#pragma unroll
        for (int j = 0; j < 8; j++) acc[i][j] = 0.f;

    for (int pass = 0; pass < 2; pass++) {
        const float* Ap = pass ? A2 : A;
        const float* Bp = pass ? B2 : B;
        int          Kp = pass ? K2 : K;
        if (Ap == nullptr) break;

        for (int k0 = 0; k0 < Kp; k0 += 16) {
            // A tile: 128x16, coalesced along K
#pragma unroll
            for (int l = 0; l < 8; l++) {
                int i  = tid + l * 256;
                int m  = i >> 4;
                int kk = i & 15;
                int gm = rowBase + m, gk = k0 + kk;
                As[kk][m] = (gm < M && gk < Kp) ? Ap[(size_t)gm * Kp + gk] : 0.f;
            }
            // B tile: 16x128, coalesced along N
#pragma unroll
            for (int l = 0; l < 8; l++) {
                int i  = tid + l * 256;
                int kk = i >> 7;
                int n  = i & 127;
                int gk = k0 + kk, gn = colBase + n;
                Bs[kk][n] = (gk < Kp && gn < N) ? Bp[(size_t)gk * N + gn] : 0.f;
            }
            __syncthreads();
#pragma unroll
            for (int kk = 0; kk < 16; kk++) {
                float a[8], b[8];
                *(float4*)&a[0] = *(const float4*)&As[kk][trow * 8];
                *(float4*)&a[4] = *(const float4*)&As[kk][trow * 8 + 4];
                *(float4*)&b[0] = *(const float4*)&Bs[kk][tcol * 8];
                *(float4*)&b[4] = *(const float4*)&Bs[kk][tcol * 8 + 4];
#pragma unroll
                for (int i = 0; i < 8; i++)
#pragma unroll
                    for (int j = 0; j < 8; j++)
                        acc[i][j] = fmaf(a[i], b[j], acc[i][j]);
            }
            __syncthreads();
        }
    }

#pragma unroll
    for (int i = 0; i < 8; i++) {
        int gm = rowBase + trow * 8 + i;
        if (gm >= M) continue;
#pragma unroll
        for (int j = 0; j < 8; j++) {
            int gn = colBase + tcol * 8 + j;
            if (gn >= N) continue;
            float v = acc[i][j];
            if (bias) v += bias[gn];
            if (Cadd) v += Cadd[(size_t)gm * N + gn];
            if (act)  v = tanhf(v);
            C[(size_t)gm * N + gn] = v;
        }
    }
}

// ------------------------ LSTM pointwise cell ------------------------------
// gates (rows x 4H) = gx + gh? + b0 + b1, torch order [i|f|g|o].
// c_in == nullptr -> initial cell state = 0.
__global__ void lstm_cell_kernel(int rows, int H,
                                 const float* __restrict__ gx,
                                 const float* __restrict__ gh,
                                 const float* __restrict__ b0,
                                 const float* __restrict__ b1,
                                 const float* __restrict__ c_in,
                                 float* __restrict__ c_out,
                                 float* __restrict__ h_out,
                                 float* __restrict__ h_copy)
{
    int idx = blockIdx.x * blockDim.x + threadIdx.x;
    if (idx >= rows * H) return;
    int r = idx / H, j = idx - r * H;
    size_t base = (size_t)r * 4 * H + j;

    float gi = gx[base]             + b0[j]         + b1[j];
    float gf = gx[base + H]         + b0[j + H]     + b1[j + H];
    float gg = gx[base + 2 * H]     + b0[j + 2 * H] + b1[j + 2 * H];
    float go = gx[base + 3 * H]     + b0[j + 3 * H] + b1[j + 3 * H];
    if (gh) {
        gi += gh[base];
        gf += gh[base + H];
        gg += gh[base + 2 * H];
        go += gh[base + 3 * H];
    }
    float c = c_in ? c_in[idx] : 0.f;
    c = sigm(gf) * c + sigm(gi) * tanhf(gg);
    float h = sigm(go) * tanhf(c);
    c_out[idx] = c;
    h_out[idx] = h;
    if (h_copy) h_copy[idx] = h;
}

// ------------------------ decoder input pack -------------------------------
// decin row r = s*1024 + u*512 + b, cols: [0,512) = c[u,b,:], [512,770) = prev
// prev(u,s) = (u*16+s == 0) ? onehot(0) : x[u*16+s-1]
__global__ void pack_decin_kernel(const float* __restrict__ x,
                                  const float* __restrict__ c,
                                  float* __restrict__ decin)
{
    size_t idx = (size_t)blockIdx.x * blockDim.x + threadIdx.x;
    const size_t total = (size_t)16 * 1024 * 770;
    if (idx >= total) return;
    int col = (int)(idx % 770);
    int r   = (int)(idx / 770);
    int b = r & 511;
    int u = (r >> 9) & 1;
    int s = r >> 10;
    float v;
    if (col < 512) {
        v = c[(size_t)(u * 512 + b) * 512 + col];
    } else {
        int vv = col - 512;
        int t  = u * 16 + s;
        if (t == 0) v = (vv == 0) ? 1.f : 0.f;
        else        v = x[((size_t)(t - 1) * 512 + b) * 258 + vv];
    }
    decin[idx] = v;
}

// ------------------------ log_softmax + permuted store ---------------------
// logits rows r = s*1024 + u*512 + b -> out[b, u*16+s, :]
__global__ void logsoftmax_kernel(const float* __restrict__ logits,
                                  float* __restrict__ out)
{
    int r = blockIdx.x;
    const float* row = logits + (size_t)r * 258;
    __shared__ float red[256];
    int tid = threadIdx.x;

    float lmax = -1e30f;
    for (int v = tid; v < 258; v += 256) lmax = fmaxf(lmax, row[v]);
    red[tid] = lmax;
    __syncthreads();
    for (int st = 128; st > 0; st >>= 1) {
        if (tid < st) red[tid] = fmaxf(red[tid], red[tid + st]);
        __syncthreads();
    }
    float m = red[0];
    __syncthreads();

    float lsum = 0.f;
    for (int v = tid; v < 258; v += 256) lsum += expf(row[v] - m);
    red[tid] = lsum;
    __syncthreads();
    for (int st = 128; st > 0; st >>= 1) {
        if (tid < st) red[tid] += red[tid + st];
        __syncthreads();
    }
    float lse = m + logf(red[0]);

    int b = r & 511;
    int u = (r >> 9) & 1;
    int s = r >> 10;
    int seq = u * 16 + s;
    float* o = out + ((size_t)b * 32 + seq) * 258;
    for (int v = tid; v < 258; v += 256) o[v] = row[v] - lse;
}

// ------------------------ host orchestration -------------------------------
static inline void gemm(int M, int N, int K,
                        const float* A, const float* B,
                        const float* bias, const float* Cadd,
                        float* C, int act,
                        const float* A2 = nullptr, const float* B2 = nullptr,
                        int K2 = 0)
{
    dim3 grid((N + 127) / 128, (M + 127) / 128);
    sgemm_kernel<<<grid, 256>>>(M, N, K, A, B, A2, B2, K2, bias, Cadd, C, act);
}

static inline void cell(int rows, int H,
                        const float* gx, const float* gh,
                        const float* b0, const float* b1,
                        const float* c_in, float* c_out,
                        float* h_out, float* h_copy)
{
    int total = rows * H;
    lstm_cell_kernel<<<(total + 255) / 256, 256>>>(rows, H, gx, gh, b0, b1,
                                                   c_in, c_out, h_out, h_copy);
}

extern "C" void kernel_launch(void* const* d_in, const int* in_sizes, int n_in,
                              void* d_out, int out_size)
{
    const float* z    = (const float*)d_in[0];
    const float* x    = (const float*)d_in[1];
    const float* cin  = (const float*)d_in[2];
    const float* ciW  = (const float*)d_in[3];
    const float* cib  = (const float*)d_in[4];
    const float* cW1i = (const float*)d_in[5];
    const float* cW1h = (const float*)d_in[6];
    const float* cb1i = (const float*)d_in[7];
    const float* cb1h = (const float*)d_in[8];
    const float* cW2i = (const float*)d_in[9];
    const float* cW2h = (const float*)d_in[10];
    const float* cb2i = (const float*)d_in[11];
    const float* cb2h = (const float*)d_in[12];
    const float* coW  = (const float*)d_in[13];
    const float* cob  = (const float*)d_in[14];
    const float* diW  = (const float*)d_in[15];
    const float* dib  = (const float*)d_in[16];
    const float* dW1i = (const float*)d_in[17];
    const float* dW1h = (const float*)d_in[18];
    const float* db1i = (const float*)d_in[19];
    const float* db1h = (const float*)d_in[20];
    const float* dW2i = (const float*)d_in[21];
    const float* dW2h = (const float*)d_in[22];
    const float* db2i = (const float*)d_in[23];
    const float* db2h = (const float*)d_in[24];
    const float* fcW  = (const float*)d_in[25];
    const float* fcb  = (const float*)d_in[26];
    float* out = (float*)d_out;

    float* S = nullptr;
    cudaGetSymbolAddress((void**)&S, g_scratch);

    float* h1c   = S + OFF_H1C;
    float* c1c   = S + OFF_C1C;
    float* h2c   = S + OFF_H2C;
    float* c2c   = S + OFF_C2C;
    float* cpre  = S + OFF_CPRE;
    float* ch    = S + OFF_CH;
    float* cvec  = S + OFF_CVEC;
    float* h1    = S + OFF_H1;
    float* c1    = S + OFF_C1;
    float* h2    = S + OFF_H2;
    float* c2    = S + OFF_C2;
    float* t1b   = S + OFF_T1;
    float* t2b   = S + OFF_T2;
    float* decin = S + OFF_DECIN;
    float* dpre  = S + OFF_DPRE;
    float* hs    = S + OFF_HS;
    float* logb  = S + OFF_LOG;

    // --- conductor init ---
    gemm(512, 1024, 512, z, ciW, cib, nullptr, h1c, 1);          // h1_0 = tanh(z@ciW+b)
    gemm(512, 4096, 258, cin, cW1i, nullptr, nullptr, cpre, 0);  // constant-input proj

    // --- conductor recurrence: 2 steps, 2 layers, B=512 ---
    for (int t = 0; t < 2; t++) {
        gemm(512, 4096, 1024, h1c, cW1h, nullptr, nullptr, t1b, 0);
        cell(512, 1024, cpre, t1b, cb1i, cb1h, t ? c1c : nullptr, c1c, h1c, nullptr);
        if (t)
            gemm(512, 4096, 1024, h1c, cW2i, nullptr, nullptr, t2b, 0,
                 h2c, cW2h, 1024);                                // fused dual GEMM
        else
            gemm(512, 4096, 1024, h1c, cW2i, nullptr, nullptr, t2b, 0);
        cell(512, 1024, t2b, nullptr, cb2i, cb2h, t ? c2c : nullptr, c2c, h2c,
             ch + (size_t)t * 512 * 1024);
    }

    // --- conductor output + decoder init ---
    gemm(1024, 512, 1024, ch, coW, cob, nullptr, cvec, 0);       // c = ch@coW+b
    gemm(1024, 1024, 512, cvec, diW, dib, nullptr, h1, 1);       // h1_0 = tanh(c@diW+b)

    // --- decoder input projections (all teacher-forced steps at once) ---
    {
        size_t total = (size_t)16 * 1024 * 770;
        pack_decin_kernel<<<(unsigned)((total + 255) / 256), 256>>>(x, cvec, decin);
    }
    gemm(16384, 4096, 770, decin, dW1i, nullptr, nullptr, dpre, 0);

    // --- decoder recurrence: 16 steps, both segments batched (rows=1024) ---
    for (int s = 0; s < 16; s++) {
        gemm(1024, 4096, 1024, h1, dW1h, nullptr, nullptr, t1b, 0);
        cell(1024, 1024, dpre + (size_t)s * 1024 * 4096, t1b, db1i, db1h,
             s ? c1 : nullptr, c1, h1, nullptr);
        if (s)
            gemm(1024, 4096, 1024, h1, dW2i, nullptr, nullptr, t2b, 0,
                 h2, dW2h, 1024);                                 // fused dual GEMM
        else
            gemm(1024, 4096, 1024, h1, dW2i, nullptr, nullptr, t2b, 0);
        cell(1024, 1024, t2b, nullptr, db2i, db2h,
             s ? c2 : nullptr, c2, h2, hs + (size_t)s * 1024 * 1024);
    }

    // --- output head ---
    gemm(16384, 258, 1024, hs, fcW, fcb, nullptr, logb, 0);
    logsoftmax_kernel<<<16384, 256>>>(logb, out);
}

// round 3
// speedup vs baseline: 1.0029x; 1.0029x over previous
#include <cuda_runtime.h>
#include <math.h>

// ---------------------------------------------------------------------------
// Decoder_29678224015654: MusicVAE-style hierarchical LSTM decoder.
// SEQ=32, SUB=16, U=2, B=512, V=258, Z=512, CH=1024, CO=512, DH=1024.
//
//  1. h1c = tanh(z @ ci_W + ci_b)
//  2. cpre = conductor_input @ cW1i  (same every conductor step)
//  3. conductor: 2 steps x 2 LSTM layers (B=512)
//  4. c = ch @ co_W + co_b ; decoder h1_0 = tanh(c @ di_W + di_b)
//  5. dec_in pack (teacher forcing) -> one big GEMM dpre = dec_in @ dW1i
//  6. decoder recurrence: 16 steps, both segments batched (rows = 1024)
//  7. logits = hs @ fc_W + fc_b ; log_softmax ; permuted store to out
// ---------------------------------------------------------------------------

// ------------------------ scratch layout (floats) --------------------------
static constexpr size_t OFF_H1C   = 0;                                   // 512*1024
static constexpr size_t OFF_C1C   = OFF_H1C   + (size_t)512*1024;
static constexpr size_t OFF_H2C   = OFF_C1C   + (size_t)512*1024;
static constexpr size_t OFF_C2C   = OFF_H2C   + (size_t)512*1024;
static constexpr size_t OFF_CPRE  = OFF_C2C   + (size_t)512*1024;        // 512*4096
static constexpr size_t OFF_CH    = OFF_CPRE  + (size_t)512*4096;        // 2*512*1024
static constexpr size_t OFF_CVEC  = OFF_CH    + (size_t)2*512*1024;      // 1024*512
static constexpr size_t OFF_H1    = OFF_CVEC  + (size_t)1024*512;        // 1024*1024
static constexpr size_t OFF_C1    = OFF_H1    + (size_t)1024*1024;
static constexpr size_t OFF_H2    = OFF_C1    + (size_t)1024*1024;
static constexpr size_t OFF_C2    = OFF_H2    + (size_t)1024*1024;
static constexpr size_t OFF_T1    = OFF_C2    + (size_t)1024*1024;       // 1024*4096
static constexpr size_t OFF_T2    = OFF_T1    + (size_t)1024*4096;       // 1024*4096
static constexpr size_t OFF_DECIN = OFF_T2    + (size_t)1024*4096;       // 16384*770
static constexpr size_t OFF_DPRE  = OFF_DECIN + (size_t)16384*770;       // 16384*4096
static constexpr size_t OFF_HS    = OFF_DPRE  + (size_t)16384*4096;      // 16384*1024
static constexpr size_t OFF_LOG   = OFF_HS    + (size_t)16384*1024;      // 16384*258
static constexpr size_t SCRATCH_TOTAL = OFF_LOG + (size_t)16384*258;

__device__ float g_scratch[SCRATCH_TOTAL];

__device__ __forceinline__ float sigm(float x) { return 1.f / (1.f + expf(-x)); }

// ------------------------ generic SGEMM -----------------------------------
// C[M,N] = act( A@B (+ A2@B2) + bias[N]? + Cadd[M,N]? ), act: 0=none 1=tanh
// 128x128 tile, BK=16, 256 threads, 8x8 per thread.
__global__ __launch_bounds__(256, 2)
void sgemm_kernel(int M, int N, int K,
                  const float* __restrict__ A,
                  const float* __restrict__ B,
                  const float* __restrict__ A2,
                  const float* __restrict__ B2,
                  int K2,
                  const float* __restrict__ bias,
                  const float* __restrict__ Cadd,
                  float* __restrict__ C,
                  int act)
{
    __shared__ __align__(16) float As[16][132];
    __shared__ __align__(16) float Bs[16][128];

    const int tid  = threadIdx.x;
    const int tcol = tid & 15;   // N direction (x8)
    const int trow = tid >> 4;   // M direction (x8)
    const int rowBase = blockIdx.y * 128;
    const int colBase = blockIdx.x * 128;

    float acc[8][8];
#pragma unroll
    for (int i = 0; i < 8; i++)
#pragma unroll
        for (int j = 0; j < 8; j++) acc[i][j] = 0.f;

    for (int pass = 0; pass < 2; pass++) {
        const float* Ap = pass ? A2 : A;
        const float* Bp = pass ? B2 : B;
        int          Kp = pass ? K2 : K;
        if (Ap == nullptr) break;

        for (int k0 = 0; k0 < Kp; k0 += 16) {
            // A tile: 128x16, coalesced along K
#pragma unroll
            for (int l = 0; l < 8; l++) {
                int i  = tid + l * 256;
                int m  = i >> 4;
                int kk = i & 15;
                int gm = rowBase + m, gk = k0 + kk;
                As[kk][m] = (gm < M && gk < Kp) ? Ap[(size_t)gm * Kp + gk] : 0.f;
            }
            // B tile: 16x128, coalesced along N
#pragma unroll
            for (int l = 0; l < 8; l++) {
                int i  = tid + l * 256;
                int kk = i >> 7;
                int n  = i & 127;
                int gk = k0 + kk, gn = colBase + n;
                Bs[kk][n] = (gk < Kp && gn < N) ? Bp[(size_t)gk * N + gn] : 0.f;
            }
            __syncthreads();
#pragma unroll
            for (int kk = 0; kk < 16; kk++) {
                float a[8], b[8];
                *(float4*)&a[0] = *(const float4*)&As[kk][trow * 8];
                *(float4*)&a[4] = *(const float4*)&As[kk][trow * 8 + 4];
                *(float4*)&b[0] = *(const float4*)&Bs[kk][tcol * 8];
                *(float4*)&b[4] = *(const float4*)&Bs[kk][tcol * 8 + 4];
#pragma unroll
                for (int i = 0; i < 8; i++)
#pragma unroll
                    for (int j = 0; j < 8; j++)
                        acc[i][j] = fmaf(a[i], b[j], acc[i][j]);
            }
            __syncthreads();
        }
    }

#pragma unroll
    for (int i = 0; i < 8; i++) {
        int gm = rowBase + trow * 8 + i;
        if (gm >= M) continue;
#pragma unroll
        for (int j = 0; j < 8; j++) {
            int gn = colBase + tcol * 8 + j;
            if (gn >= N) continue;
            float v = acc[i][j];
            if (bias) v += bias[gn];
            if (Cadd) v += Cadd[(size_t)gm * N + gn];
            if (act)  v = tanhf(v);
            C[(size_t)gm * N + gn] = v;
        }
    }
}

// ------------------------ LSTM pointwise cell ------------------------------
// gates (rows x 4H) = gx + gh? + b0 + b1, torch order [i|f|g|o].
// c_in == nullptr -> initial cell state = 0.
__global__ void lstm_cell_kernel(int rows, int H,
                                 const float* __restrict__ gx,
                                 const float* __restrict__ gh,
                                 const float* __restrict__ b0,
                                 const float* __restrict__ b1,
                                 const float* __restrict__ c_in,
                                 float* __restrict__ c_out,
                                 float* __restrict__ h_out,
                                 float* __restrict__ h_copy)
{
    int idx = blockIdx.x * blockDim.x + threadIdx.x;
    if (idx >= rows * H) return;
    int r = idx / H, j = idx - r * H;
    size_t base = (size_t)r * 4 * H + j;

    float gi = gx[base]             + b0[j]         + b1[j];
    float gf = gx[base + H]         + b0[j + H]     + b1[j + H];
    float gg = gx[base + 2 * H]     + b0[j + 2 * H] + b1[j + 2 * H];
    float go = gx[base + 3 * H]     + b0[j + 3 * H] + b1[j + 3 * H];
    if (gh) {
        gi += gh[base];
        gf += gh[base + H];
        gg += gh[base + 2 * H];
        go += gh[base + 3 * H];
    }
    float c = c_in ? c_in[idx] : 0.f;
    c = sigm(gf) * c + sigm(gi) * tanhf(gg);
    float h = sigm(go) * tanhf(c);
    c_out[idx] = c;
    h_out[idx] = h;
    if (h_copy) h_copy[idx] = h;
}

// ------------------------ decoder input pack -------------------------------
// decin row r = s*1024 + u*512 + b, cols: [0,512) = c[u,b,:], [512,770) = prev
// prev(u,s) = (u*16+s == 0) ? onehot(0) : x[u*16+s-1]
__global__ void pack_decin_kernel(const float* __restrict__ x,
                                  const float* __restrict__ c,
                                  float* __restrict__ decin)
{
    size_t idx = (size_t)blockIdx.x * blockDim.x + threadIdx.x;
    const size_t total = (size_t)16 * 1024 * 770;
    if (idx >= total) return;
    int col = (int)(idx % 770);
    int r   = (int)(idx / 770);
    int b = r & 511;
    int u = (r >> 9) & 1;
    int s = r >> 10;
    float v;
    if (col < 512) {
        v = c[(size_t)(u * 512 + b) * 512 + col];
    } else {
        int vv = col - 512;
        int t  = u * 16 + s;
        if (t == 0) v = (vv == 0) ? 1.f : 0.f;
        else        v = x[((size_t)(t - 1) * 512 + b) * 258 + vv];
    }
    decin[idx] = v;
}

// ------------------------ log_softmax + permuted store ---------------------
// logits rows r = s*1024 + u*512 + b -> out[b, u*16+s, :]
__global__ void logsoftmax_kernel(const float* __restrict__ logits,
                                  float* __restrict__ out)
{
    int r = blockIdx.x;
    const float* row = logits + (size_t)r * 258;
    __shared__ float red[256];
    int tid = threadIdx.x;

    float lmax = -1e30f;
    for (int v = tid; v < 258; v += 256) lmax = fmaxf(lmax, row[v]);
    red[tid] = lmax;
    __syncthreads();
    for (int st = 128; st > 0; st >>= 1) {
        if (tid < st) red[tid] = fmaxf(red[tid], red[tid + st]);
        __syncthreads();
    }
    float m = red[0];
    __syncthreads();

    float lsum = 0.f;
    for (int v = tid; v < 258; v += 256) lsum += expf(row[v] - m);
    red[tid] = lsum;
    __syncthreads();
    for (int st = 128; st > 0; st >>= 1) {
        if (tid < st) red[tid] += red[tid + st];
        __syncthreads();
    }
    float lse = m + logf(red[0]);

    int b = r & 511;
    int u = (r >> 9) & 1;
    int s = r >> 10;
    int seq = u * 16 + s;
    float* o = out + ((size_t)b * 32 + seq) * 258;
    for (int v = tid; v < 258; v += 256) o[v] = row[v] - lse;
}

// ------------------------ host orchestration -------------------------------
static inline void gemm(int M, int N, int K,
                        const float* A, const float* B,
                        const float* bias, const float* Cadd,
                        float* C, int act,
                        const float* A2 = nullptr, const float* B2 = nullptr,
                        int K2 = 0)
{
    dim3 grid((N + 127) / 128, (M + 127) / 128);
    sgemm_kernel<<<grid, 256>>>(M, N, K, A, B, A2, B2, K2, bias, Cadd, C, act);
}

static inline void cell(int rows, int H,
                        const float* gx, const float* gh,
                        const float* b0, const float* b1,
                        const float* c_in, float* c_out,
                        float* h_out, float* h_copy)
{
    int total = rows * H;
    lstm_cell_kernel<<<(total + 255) / 256, 256>>>(rows, H, gx, gh, b0, b1,
                                                   c_in, c_out, h_out, h_copy);
}

extern "C" void kernel_launch(void* const* d_in, const int* in_sizes, int n_in,
                              void* d_out, int out_size)
{
    const float* z    = (const float*)d_in[0];
    const float* x    = (const float*)d_in[1];
    const float* cin  = (const float*)d_in[2];
    const float* ciW  = (const float*)d_in[3];
    const float* cib  = (const float*)d_in[4];
    const float* cW1i = (const float*)d_in[5];
    const float* cW1h = (const float*)d_in[6];
    const float* cb1i = (const float*)d_in[7];
    const float* cb1h = (const float*)d_in[8];
    const float* cW2i = (const float*)d_in[9];
    const float* cW2h = (const float*)d_in[10];
    const float* cb2i = (const float*)d_in[11];
    const float* cb2h = (const float*)d_in[12];
    const float* coW  = (const float*)d_in[13];
    const float* cob  = (const float*)d_in[14];
    const float* diW  = (const float*)d_in[15];
    const float* dib  = (const float*)d_in[16];
    const float* dW1i = (const float*)d_in[17];
    const float* dW1h = (const float*)d_in[18];
    const float* db1i = (const float*)d_in[19];
    const float* db1h = (const float*)d_in[20];
    const float* dW2i = (const float*)d_in[21];
    const float* dW2h = (const float*)d_in[22];
    const float* db2i = (const float*)d_in[23];
    const float* db2h = (const float*)d_in[24];
    const float* fcW  = (const float*)d_in[25];
    const float* fcb  = (const float*)d_in[26];
    float* out = (float*)d_out;

    float* S = nullptr;
    cudaGetSymbolAddress((void**)&S, g_scratch);

    float* h1c   = S + OFF_H1C;
    float* c1c   = S + OFF_C1C;
    float* h2c   = S + OFF_H2C;
    float* c2c   = S + OFF_C2C;
    float* cpre  = S + OFF_CPRE;
    float* ch    = S + OFF_CH;
    float* cvec  = S + OFF_CVEC;
    float* h1    = S + OFF_H1;
    float* c1    = S + OFF_C1;
    float* h2    = S + OFF_H2;
    float* c2    = S + OFF_C2;
    float* t1b   = S + OFF_T1;
    float* t2b   = S + OFF_T2;
    float* decin = S + OFF_DECIN;
    float* dpre  = S + OFF_DPRE;
    float* hs    = S + OFF_HS;
    float* logb  = S + OFF_LOG;

    // --- conductor init ---
    gemm(512, 1024, 512, z, ciW, cib, nullptr, h1c, 1);          // h1_0 = tanh(z@ciW+b)
    gemm(512, 4096, 258, cin, cW1i, nullptr, nullptr, cpre, 0);  // constant-input proj

    // --- conductor recurrence: 2 steps, 2 layers, B=512 ---
    for (int t = 0; t < 2; t++) {
        gemm(512, 4096, 1024, h1c, cW1h, nullptr, nullptr, t1b, 0);
        cell(512, 1024, cpre, t1b, cb1i, cb1h, t ? c1c : nullptr, c1c, h1c, nullptr);
        if (t)
            gemm(512, 4096, 1024, h1c, cW2i, nullptr, nullptr, t2b, 0,
                 h2c, cW2h, 1024);                                // fused dual GEMM
        else
            gemm(512, 4096, 1024, h1c, cW2i, nullptr, nullptr, t2b, 0);
        cell(512, 1024, t2b, nullptr, cb2i, cb2h, t ? c2c : nullptr, c2c, h2c,
             ch + (size_t)t * 512 * 1024);
    }

    // --- conductor output + decoder init ---
    gemm(1024, 512, 1024, ch, coW, cob, nullptr, cvec, 0);       // c = ch@coW+b
    gemm(1024, 1024, 512, cvec, diW, dib, nullptr, h1, 1);       // h1_0 = tanh(c@diW+b)

    // --- decoder input projections (all teacher-forced steps at once) ---
    {
        size_t total = (size_t)16 * 1024 * 770;
        pack_decin_kernel<<<(unsigned)((total + 255) / 256), 256>>>(x, cvec, decin);
    }
    gemm(16384, 4096, 770, decin, dW1i, nullptr, nullptr, dpre, 0);

    // --- decoder recurrence: 16 steps, both segments batched (rows=1024) ---
    for (int s = 0; s < 16; s++) {
        gemm(1024, 4096, 1024, h1, dW1h, nullptr, nullptr, t1b, 0);
        cell(1024, 1024, dpre + (size_t)s * 1024 * 4096, t1b, db1i, db1h,
             s ? c1 : nullptr, c1, h1, nullptr);
        if (s)
            gemm(1024, 4096, 1024, h1, dW2i, nullptr, nullptr, t2b, 0,
                 h2, dW2h, 1024);                                 // fused dual GEMM
        else
            gemm(1024, 4096, 1024, h1, dW2i, nullptr, nullptr, t2b, 0);
        cell(1024, 1024, t2b, nullptr, db2i, db2h,
             s ? c2 : nullptr, c2, h2, hs + (size_t)s * 1024 * 1024);
    }

    // --- output head ---
    gemm(16384, 258, 1024, hs, fcW, fcb, nullptr, logb, 0);
    logsoftmax_kernel<<<16384, 256>>>(logb, out);
}

// round 6
// speedup vs baseline: 2.7201x; 2.7123x over previous
#include <cuda_runtime.h>
#include <cuda_bf16.h>
#include <math.h>
#include <stdint.h>

typedef __nv_bfloat16 bf16;

// ----------------------------- PTX helpers --------------------------------
__device__ __forceinline__ uint32_t smem_u32(const void* p) {
    uint32_t a;
    asm("{ .reg .u64 t; cvta.to.shared.u64 t, %1; cvt.u32.u64 %0, t; }" : "=r"(a) : "l"(p));
    return a;
}
__device__ __forceinline__ void cp16(uint32_t d, const void* s) {
    asm volatile("cp.async.cg.shared.global [%0], [%1], 16;" :: "r"(d), "l"(s) : "memory");
}
#define CP_COMMIT() asm volatile("cp.async.commit_group;" ::: "memory")
#define CP_WAIT0()  asm volatile("cp.async.wait_group 0;" ::: "memory")
#define CP_WAIT1()  asm volatile("cp.async.wait_group 1;" ::: "memory")

__device__ __forceinline__ void ldsm4(uint32_t* r, uint32_t addr) {
    asm volatile("ldmatrix.sync.aligned.m8n8.x4.shared.b16 {%0,%1,%2,%3}, [%4];"
                 : "=r"(r[0]), "=r"(r[1]), "=r"(r[2]), "=r"(r[3]) : "r"(addr));
}
__device__ __forceinline__ void mma_bf16(float* c, const uint32_t* a, const uint32_t* b) {
    asm volatile(
        "mma.sync.aligned.m16n8k16.row.col.f32.bf16.bf16.f32 "
        "{%0,%1,%2,%3}, {%4,%5,%6,%7}, {%8,%9}, {%0,%1,%2,%3};"
        : "+f"(c[0]), "+f"(c[1]), "+f"(c[2]), "+f"(c[3])
        : "r"(a[0]), "r"(a[1]), "r"(a[2]), "r"(a[3]), "r"(b[0]), "r"(b[1]));
}
__device__ __forceinline__ float sigm(float x) { return 1.f / (1.f + expf(-x)); }

// ----------------------------- scratch ------------------------------------
#define DA __device__ __align__(128)
DA float g_dpre[(size_t)16384 * 4096];
DA float g_cpre[(size_t)512 * 4096];
DA float g_cvec[1024 * 512];
DA float g_ch[(size_t)1024 * 1024];
DA float g_c1[1024 * 1024], g_c2[1024 * 1024], g_c1c[512 * 1024], g_c2c[512 * 1024];
DA float g_logb[(size_t)16384 * 258];
DA bf16 g_hc_hi[2][(size_t)1024 * 2048], g_hc_lo[2][(size_t)1024 * 2048];   // decoder concat [h1|h2]
DA bf16 g_hcc_hi[2][(size_t)512 * 2048], g_hcc_lo[2][(size_t)512 * 2048];   // conductor concat
DA bf16 g_hs_hi[(size_t)16384 * 1024], g_hs_lo[(size_t)16384 * 1024];
DA bf16 g_din_hi[(size_t)16384 * 832], g_din_lo[(size_t)16384 * 832];
DA bf16 g_cin_hi[512 * 320], g_cin_lo[512 * 320];
DA bf16 g_cW1h_t[2][(size_t)4096 * 1024], g_cW2_t[2][(size_t)4096 * 2048], g_cW1i_t[2][(size_t)4096 * 320];
DA bf16 g_dW1h_t[2][(size_t)4096 * 1024], g_dW2_t[2][(size_t)4096 * 2048], g_dW1i_t[2][(size_t)4096 * 832];
DA bf16 g_fcW_t[2][(size_t)512 * 1024];
DA float g_b1c[4096], g_b2c[4096], g_b1d[4096], g_b2d[4096], g_fcbp[512];

// ----------------- mma.sync GEMM, 128x128 tile, BK=64 ----------------------
// C = Ahi@Bhi + Ahi@Blo + Alo@Bhi over K (mult of 64); B stored [Nrows,K].
// perm=1: tile col r -> weight row (r>>5)*1024 + nt*32 + (r&31)  (gate-major
//         blocks of 32 units per tile; gate = bits 5..6 of tile col).
// Epilogue: Cst!=0 -> plain fp32 store; else fused LSTM cell (gate-major
// bias/Cadd indexed [g*1024+u]).
// Warps: 2(M) x 4(N); warp wn owns n-blocks {wn,wn+4,wn+8,wn+12} so all 4
// gates of a unit land in one thread.
static constexpr int HG_SMEM = 2 * 65536;  // 2 stages x (Ahi|Alo|Bhi|Blo) 16KB each

__global__ __launch_bounds__(256, 1)
void hgemm(const bf16* __restrict__ Ahi, const bf16* __restrict__ Alo, int lda, int K,
           const bf16* __restrict__ Bhi, const bf16* __restrict__ Blo, int perm,
           const float* __restrict__ bias, const float* __restrict__ Cadd, int ldc,
           float* __restrict__ Cst, int Nlog, int ldcp,
           float* __restrict__ cstate,
           bf16* __restrict__ Hhi, bf16* __restrict__ Hlo, int ldh,
           bf16* __restrict__ H2hi, bf16* __restrict__ H2lo,
           float* __restrict__ Hf)
{
    extern __shared__ char smem_raw[];
    const uint32_t sb = smem_u32(smem_raw);
    const int tid = threadIdx.x, nt = blockIdx.x, m0 = blockIdx.y * 128;
    const int wid = tid >> 5, lane = tid & 31;
    const int wm = wid & 1, wn = wid >> 1;

    // B tile row -> global weight row
    int brow[4];
#pragma unroll
    for (int i = 0; i < 4; i++) {
        int r = (tid + i * 256) >> 3;
        brow[i] = perm ? ((r >> 5) * 1024 + nt * 32 + (r & 31)) : (nt * 128 + r);
    }
    const int nk = K >> 6;

    auto load_stage = [&](int st, int k0) {
        const uint32_t base = sb + st * 65536;
#pragma unroll
        for (int i = 0; i < 4; i++) {
            int c = tid + i * 256, row = c >> 3, ch = c & 7;
            uint32_t so = (uint32_t)((row << 7) + ((ch ^ (row & 7)) << 4));
            size_t gA = (size_t)(m0 + row) * lda + k0 + ch * 8;
            cp16(base + so,         Ahi + gA);
            cp16(base + 16384 + so, Alo + gA);
            size_t gB = (size_t)brow[i] * K + k0 + ch * 8;
            cp16(base + 32768 + so, Bhi + gB);
            cp16(base + 49152 + so, Blo + gB);
        }
        CP_COMMIT();
    };

    float acc[4][4][4];
#pragma unroll
    for (int a = 0; a < 4; a++)
#pragma unroll
        for (int b = 0; b < 4; b++)
#pragma unroll
            for (int c = 0; c < 4; c++) acc[a][b][c] = 0.f;

    load_stage(0, 0);

    // per-lane ldmatrix address components
    const int lrowA = (lane & 7) + (((lane >> 3) & 1) << 3);  // 0..15
    const int kselA = lane >> 4;                              // 0/1 (k-half)
    const int jselB = lane >> 4;                              // 0/1 (gate in pair)
    const int kselB = (lane >> 3) & 1;                        // 0/1 (k-half)
    const int nrB   = lane & 7;

    for (int i = 0; i < nk; i++) {
        const int st = i & 1;
        if (i + 1 < nk) { load_stage(1 - st, (i + 1) << 6); CP_WAIT1(); }
        else            { CP_WAIT0(); }
        __syncthreads();

        const uint32_t base = sb + st * 65536;
#pragma unroll
        for (int kk = 0; kk < 4; kk++) {     // four k16 steps inside BK=64
            uint32_t a_hi[4][4], a_lo[4][4], b_hi[4][2], b_lo[4][2];
#pragma unroll
            for (int mi = 0; mi < 4; mi++) {
                int r = wm * 64 + mi * 16 + lrowA;
                int ch = 2 * kk + kselA;
                uint32_t ad = base + (uint32_t)((r << 7) + ((ch ^ (r & 7)) << 4));
                ldsm4(a_hi[mi], ad);
                ldsm4(a_lo[mi], ad + 16384);
            }
#pragma unroll
            for (int jp = 0; jp < 2; jp++) {
                int j = 2 * jp + jselB;
                int nr = (wn + 4 * j) * 8 + nrB;
                int ch = 2 * kk + kselB;
                uint32_t ad = base + 32768 + (uint32_t)((nr << 7) + ((ch ^ (nr & 7)) << 4));
                ldsm4(&b_hi[2 * jp][0], ad);
                ldsm4(&b_lo[2 * jp][0], ad + 16384);
            }
#pragma unroll
            for (int mi = 0; mi < 4; mi++)
#pragma unroll
                for (int j = 0; j < 4; j++) {
                    mma_bf16(acc[mi][j], a_hi[mi], b_hi[j]);
                    mma_bf16(acc[mi][j], a_hi[mi], b_lo[j]);
                    mma_bf16(acc[mi][j], a_lo[mi], b_hi[j]);
                }
        }
        __syncthreads();
    }

    // ------------------------------ epilogue -------------------------------
    const int qr = lane >> 2, qc = (lane & 3) * 2;
#pragma unroll
    for (int mi = 0; mi < 4; mi++)
#pragma unroll
        for (int half = 0; half < 2; half++) {
            const int row = m0 + wm * 64 + mi * 16 + qr + half * 8;
            if (Cst) {
#pragma unroll
                for (int j = 0; j < 4; j++)
#pragma unroll
                    for (int ci = 0; ci < 2; ci++) {
                        float v = acc[mi][j][half * 2 + ci];
                        if (perm) {
                            int pst = j * 1024 + nt * 32 + wn * 8 + qc + ci;
                            Cst[(size_t)row * ldcp + pst] = v;
                        } else {
                            int p = nt * 128 + j * 32 + wn * 8 + qc + ci;
                            if (p < Nlog) {
                                if (bias) v += bias[p];
                                Cst[(size_t)row * ldcp + p] = v;
                            }
                        }
                    }
            } else {
                const int u0 = nt * 32 + wn * 8 + qc;
                float2 cold = *(const float2*)&cstate[(size_t)row * 1024 + u0];
                float hv[2];
#pragma unroll
                for (int ci = 0; ci < 2; ci++) {
                    const int u = u0 + ci;
                    float gi = acc[mi][0][half * 2 + ci] + bias[u];
                    float gf = acc[mi][1][half * 2 + ci] + bias[1024 + u];
                    float gg = acc[mi][2][half * 2 + ci] + bias[2048 + u];
                    float go = acc[mi][3][half * 2 + ci] + bias[3072 + u];
                    if (Cadd) {
                        const float* ca = Cadd + (size_t)row * ldc;
                        gi += ca[u]; gf += ca[1024 + u];
                        gg += ca[2048 + u]; go += ca[3072 + u];
                    }
                    float cold_v = ci ? cold.y : cold.x;
                    float cn = sigm(gf) * cold_v + sigm(gi) * tanhf(gg);
                    hv[ci] = sigm(go) * tanhf(cn);
                    if (ci) cold.y = cn; else cold.x = cn;
                }
                *(float2*)&cstate[(size_t)row * 1024 + u0] = cold;
                bf16 h0 = __float2bfloat16(hv[0]), h1 = __float2bfloat16(hv[1]);
                bf16 l0 = __float2bfloat16(hv[0] - __bfloat162float(h0));
                bf16 l1 = __float2bfloat16(hv[1] - __bfloat162float(h1));
                uint32_t hp = (uint32_t)__bfloat16_as_ushort(h0) |
                              ((uint32_t)__bfloat16_as_ushort(h1) << 16);
                uint32_t lp = (uint32_t)__bfloat16_as_ushort(l0) |
                              ((uint32_t)__bfloat16_as_ushort(l1) << 16);
                *(uint32_t*)&Hhi[(size_t)row * ldh + u0] = hp;
                *(uint32_t*)&Hlo[(size_t)row * ldh + u0] = lp;
                if (H2hi) {
                    *(uint32_t*)&H2hi[(size_t)row * 1024 + u0] = hp;
                    *(uint32_t*)&H2lo[(size_t)row * 1024 + u0] = lp;
                }
                if (Hf) {
                    Hf[(size_t)row * 1024 + u0]     = hv[0];
                    Hf[(size_t)row * 1024 + u0 + 1] = hv[1];
                }
            }
        }
}

// ------------------------- small SIMT SGEMM --------------------------------
__global__ __launch_bounds__(256, 2)
void sgemm_kernel(int M, int N, int K, const float* __restrict__ A, const float* __restrict__ B,
                  const float* __restrict__ bias, float* __restrict__ C, int act,
                  bf16* __restrict__ ohi, bf16* __restrict__ olo, int ldo)
{
    __shared__ __align__(16) float As[16][132], Bs[16][128];
    const int tid = threadIdx.x, tc = tid & 15, tr = tid >> 4;
    const int rb = blockIdx.y * 128, cb = blockIdx.x * 128;
    float acc[8][8];
#pragma unroll
    for (int i = 0; i < 8; i++)
#pragma unroll
        for (int j = 0; j < 8; j++) acc[i][j] = 0.f;
    for (int k0 = 0; k0 < K; k0 += 16) {
#pragma unroll
        for (int l = 0; l < 8; l++) {
            int i = tid + l * 256, m = i >> 4, kk = i & 15;
            int gm = rb + m, gk = k0 + kk;
            As[kk][m] = (gm < M && gk < K) ? A[(size_t)gm * K + gk] : 0.f;
        }
#pragma unroll
        for (int l = 0; l < 8; l++) {
            int i = tid + l * 256, kk = i >> 7, n = i & 127;
            int gk = k0 + kk, gn = cb + n;
            Bs[kk][n] = (gk < K && gn < N) ? B[(size_t)gk * N + gn] : 0.f;
        }
        __syncthreads();
#pragma unroll
        for (int kk = 0; kk < 16; kk++) {
            float a[8], b[8];
            *(float4*)&a[0] = *(const float4*)&As[kk][tr * 8];
            *(float4*)&a[4] = *(const float4*)&As[kk][tr * 8 + 4];
            *(float4*)&b[0] = *(const float4*)&Bs[kk][tc * 8];
            *(float4*)&b[4] = *(const float4*)&Bs[kk][tc * 8 + 4];
#pragma unroll
            for (int i = 0; i < 8; i++)
#pragma unroll
                for (int j = 0; j < 8; j++) acc[i][j] = fmaf(a[i], b[j], acc[i][j]);
        }
        __syncthreads();
    }
#pragma unroll
    for (int i = 0; i < 8; i++) {
        int gm = rb + tr * 8 + i;
        if (gm >= M) continue;
#pragma unroll
        for (int j = 0; j < 8; j++) {
            int gn = cb + tc * 8 + j;
            if (gn >= N) continue;
            float v = acc[i][j];
            if (bias) v += bias[gn];
            if (act) v = tanhf(v);
            if (C) C[(size_t)gm * N + gn] = v;
            if (ohi) {
                bf16 h = __float2bfloat16(v);
                ohi[(size_t)gm * ldo + gn] = h;
                olo[(size_t)gm * ldo + gn] = __float2bfloat16(v - __bfloat162float(h));
            }
        }
    }
}

// -------------------- transpose + bf16 split, zero-padded -------------------
__global__ void tsplit_kernel(const float* __restrict__ src, bf16* __restrict__ dhi,
                              bf16* __restrict__ dlo, int Ksrc, int Nsrc,
                              int src_ld, int ldd, int col0)
{
    __shared__ float t[32][33];
    const int k0 = blockIdx.x * 32, n0 = blockIdx.y * 32;
#pragma unroll
    for (int y = 0; y < 4; y++) {
        int k = k0 + threadIdx.y + y * 8, n = n0 + threadIdx.x;
        t[threadIdx.y + y * 8][threadIdx.x] = (k < Ksrc && n < Nsrc) ? src[(size_t)k * src_ld + n] : 0.f;
    }
    __syncthreads();
#pragma unroll
    for (int y = 0; y < 4; y++) {
        int n = n0 + threadIdx.y + y * 8, k = k0 + threadIdx.x;
        float w = t[threadIdx.x][threadIdx.y + y * 8];
        bf16 h = __float2bfloat16(w);
        dhi[(size_t)n * ldd + col0 + k] = h;
        dlo[(size_t)n * ldd + col0 + k] = __float2bfloat16(w - __bfloat162float(h));
    }
}

__global__ void bias_comb_kernel(const float* __restrict__ b0, const float* __restrict__ b1,
                                 float* __restrict__ out, int n_out, int n_src)
{
    int p = blockIdx.x * blockDim.x + threadIdx.x;
    if (p >= n_out) return;
    float v = 0.f;
    if (p < n_src) { v = b0[p]; if (b1) v += b1[p]; }
    out[p] = v;
}

__global__ void pack_cin_kernel(const float* __restrict__ cin, bf16* dhi, bf16* dlo)
{
    int idx = blockIdx.x * blockDim.x + threadIdx.x;
    if (idx >= 512 * 320) return;
    int b = idx / 320, v = idx - b * 320;
    float x = (v < 258) ? cin[(size_t)b * 258 + v] : 0.f;
    bf16 h = __float2bfloat16(x);
    dhi[idx] = h; dlo[idx] = __float2bfloat16(x - __bfloat162float(h));
}

__global__ void pack_decin_kernel(const float* __restrict__ x, const float* __restrict__ c,
                                  bf16* dhi, bf16* dlo)
{
    size_t idx = (size_t)blockIdx.x * blockDim.x + threadIdx.x;
    if (idx >= (size_t)16384 * 832) return;
    int col = (int)(idx % 832), r = (int)(idx / 832);
    int b = r & 511, u = (r >> 9) & 1, s = r >> 10;
    float v = 0.f;
    if (col < 512) v = c[(size_t)(u * 512 + b) * 512 + col];
    else if (col < 770) {
        int vv = col - 512, t = u * 16 + s;
        v = (t == 0) ? (vv == 0 ? 1.f : 0.f) : x[((size_t)(t - 1) * 512 + b) * 258 + vv];
    }
    bf16 h = __float2bfloat16(v);
    dhi[idx] = h; dlo[idx] = __float2bfloat16(v - __bfloat162float(h));
}

__global__ void logsoftmax_kernel(const float* __restrict__ logits, float* __restrict__ out)
{
    int r = blockIdx.x;
    const float* row = logits + (size_t)r * 258;
    __shared__ float red[256];
    int tid = threadIdx.x;
    float lm = -1e30f;
    for (int v = tid; v < 258; v += 256) lm = fmaxf(lm, row[v]);
    red[tid] = lm; __syncthreads();
    for (int st = 128; st > 0; st >>= 1) { if (tid < st) red[tid] = fmaxf(red[tid], red[tid + st]); __syncthreads(); }
    float m = red[0]; __syncthreads();
    float ls = 0.f;
    for (int v = tid; v < 258; v += 256) ls += expf(row[v] - m);
    red[tid] = ls; __syncthreads();
    for (int st = 128; st > 0; st >>= 1) { if (tid < st) red[tid] += red[tid + st]; __syncthreads(); }
    float lse = m + logf(red[0]);
    int b = r & 511, u = (r >> 9) & 1, s = r >> 10;
    float* o = out + ((size_t)b * 32 + (u * 16 + s)) * 258;
    for (int v = tid; v < 258; v += 256) o[v] = row[v] - lse;
}

// ------------------------------- host --------------------------------------
static void hgg(int Ngrid, int Mtiles, const bf16* Ahi, const bf16* Alo, int lda, int K,
                const bf16* Bhi, const bf16* Blo, int perm,
                const float* bias, const float* Cadd, int ldc,
                float* Cst, int Nlog, int ldcp, float* cs,
                bf16* Hhi, bf16* Hlo, int ldh, bf16* H2hi, bf16* H2lo, float* Hf)
{
    dim3 g(Ngrid, Mtiles);
    hgemm<<<g, 256, HG_SMEM>>>(Ahi, Alo, lda, K, Bhi, Blo, perm, bias, Cadd, ldc,
                               Cst, Nlog, ldcp, cs, Hhi, Hlo, ldh, H2hi, H2lo, Hf);
}
static void tsp(const float* src, bf16* dhi, bf16* dlo, int Ksrc, int Nsrc,
                int src_ld, int Kpad, int Npad, int ldd, int col0)
{
    dim3 g(Kpad / 32, Npad / 32), b(32, 8);
    tsplit_kernel<<<g, b>>>(src, dhi, dlo, Ksrc, Nsrc, src_ld, ldd, col0);
}
#define GS(p, s) cudaGetSymbolAddress((void**)&p, s)

extern "C" void kernel_launch(void* const* d_in, const int* in_sizes, int n_in,
                              void* d_out, int out_size)
{
    const float *z = (const float*)d_in[0], *x = (const float*)d_in[1], *cin = (const float*)d_in[2];
    const float *ciW = (const float*)d_in[3], *cib = (const float*)d_in[4];
    const float *cW1i = (const float*)d_in[5], *cW1h = (const float*)d_in[6];
    const float *cb1i = (const float*)d_in[7], *cb1h = (const float*)d_in[8];
    const float *cW2i = (const float*)d_in[9], *cW2h = (const float*)d_in[10];
    const float *cb2i = (const float*)d_in[11], *cb2h = (const float*)d_in[12];
    const float *coW = (const float*)d_in[13], *cob = (const float*)d_in[14];
    const float *diW = (const float*)d_in[15], *dib = (const float*)d_in[16];
    const float *dW1i = (const float*)d_in[17], *dW1h = (const float*)d_in[18];
    const float *db1i = (const float*)d_in[19], *db1h = (const float*)d_in[20];
    const float *dW2i = (const float*)d_in[21], *dW2h = (const float*)d_in[22];
    const float *db2i = (const float*)d_in[23], *db2h = (const float*)d_in[24];
    const float *fcW = (const float*)d_in[25], *fcb = (const float*)d_in[26];
    float* out = (float*)d_out;

    cudaFuncSetAttribute(hgemm, cudaFuncAttributeMaxDynamicSharedMemorySize, HG_SMEM);

    float *dpre, *cpre, *cvec, *ch, *c1, *c2, *c1c, *c2c, *logb;
    float *b1c, *b2c, *b1d, *b2d, *fcbp;
    bf16 *hcH[2], *hcL[2], *hccH[2], *hccL[2], *hsH, *hsL, *dinH, *dinL, *cinH, *cinL;
    bf16 *cW1hT[2], *cW2T[2], *cW1iT[2], *dW1hT[2], *dW2T[2], *dW1iT[2], *fcWT[2];
    GS(dpre, g_dpre); GS(cpre, g_cpre); GS(cvec, g_cvec); GS(ch, g_ch);
    GS(c1, g_c1); GS(c2, g_c2); GS(c1c, g_c1c); GS(c2c, g_c2c); GS(logb, g_logb);
    GS(b1c, g_b1c); GS(b2c, g_b2c); GS(b1d, g_b1d); GS(b2d, g_b2d); GS(fcbp, g_fcbp);
    { bf16* p; GS(p, g_hc_hi); hcH[0] = p; hcH[1] = p + (size_t)1024 * 2048; }
    { bf16* p; GS(p, g_hc_lo); hcL[0] = p; hcL[1] = p + (size_t)1024 * 2048; }
    { bf16* p; GS(p, g_hcc_hi); hccH[0] = p; hccH[1] = p + (size_t)512 * 2048; }
    { bf16* p; GS(p, g_hcc_lo); hccL[0] = p; hccL[1] = p + (size_t)512 * 2048; }
    GS(hsH, g_hs_hi); GS(hsL, g_hs_lo); GS(dinH, g_din_hi); GS(dinL, g_din_lo);
    GS(cinH, g_cin_hi); GS(cinL, g_cin_lo);
    { bf16* p; GS(p, g_cW1h_t); cW1hT[0] = p; cW1hT[1] = p + (size_t)4096 * 1024; }
    { bf16* p; GS(p, g_cW2_t);  cW2T[0] = p;  cW2T[1] = p + (size_t)4096 * 2048; }
    { bf16* p; GS(p, g_cW1i_t); cW1iT[0] = p; cW1iT[1] = p + (size_t)4096 * 320; }
    { bf16* p; GS(p, g_dW1h_t); dW1hT[0] = p; dW1hT[1] = p + (size_t)4096 * 1024; }
    { bf16* p; GS(p, g_dW2_t);  dW2T[0] = p;  dW2T[1] = p + (size_t)4096 * 2048; }
    { bf16* p; GS(p, g_dW1i_t); dW1iT[0] = p; dW1iT[1] = p + (size_t)4096 * 832; }
    { bf16* p; GS(p, g_fcW_t);  fcWT[0] = p;  fcWT[1] = p + (size_t)512 * 1024; }

    // zero init: ping-pong buffer 1 (h2 region read at step 0) + cell states
    cudaMemsetAsync(hcH[1], 0, (size_t)1024 * 2048 * 2);
    cudaMemsetAsync(hcL[1], 0, (size_t)1024 * 2048 * 2);
    cudaMemsetAsync(hccH[1], 0, (size_t)512 * 2048 * 2);
    cudaMemsetAsync(hccL[1], 0, (size_t)512 * 2048 * 2);
    cudaMemsetAsync(c1, 0, (size_t)1024 * 1024 * 4);
    cudaMemsetAsync(c2, 0, (size_t)1024 * 1024 * 4);
    cudaMemsetAsync(c1c, 0, (size_t)512 * 1024 * 4);
    cudaMemsetAsync(c2c, 0, (size_t)512 * 1024 * 4);

    // weight prep (transpose + hi/lo split; zero-padded)
    tsp(cW1h, cW1hT[0], cW1hT[1], 1024, 4096, 4096, 1024, 4096, 1024, 0);
    tsp(cW2i, cW2T[0], cW2T[1], 1024, 4096, 4096, 1024, 4096, 2048, 0);
    tsp(cW2h, cW2T[0], cW2T[1], 1024, 4096, 4096, 1024, 4096, 2048, 1024);
    tsp(cW1i, cW1iT[0], cW1iT[1], 258, 4096, 4096, 320, 4096, 320, 0);
    tsp(dW1h, dW1hT[0], dW1hT[1], 1024, 4096, 4096, 1024, 4096, 1024, 0);
    tsp(dW2i, dW2T[0], dW2T[1], 1024, 4096, 4096, 1024, 4096, 2048, 0);
    tsp(dW2h, dW2T[0], dW2T[1], 1024, 4096, 4096, 1024, 4096, 2048, 1024);
    tsp(dW1i, dW1iT[0], dW1iT[1], 770, 4096, 4096, 832, 4096, 832, 0);
    tsp(fcW, fcWT[0], fcWT[1], 1024, 258, 258, 1024, 512, 1024, 0);
    bias_comb_kernel<<<16, 256>>>(cb1i, cb1h, b1c, 4096, 4096);
    bias_comb_kernel<<<16, 256>>>(cb2i, cb2h, b2c, 4096, 4096);
    bias_comb_kernel<<<16, 256>>>(db1i, db1h, b1d, 4096, 4096);
    bias_comb_kernel<<<16, 256>>>(db2i, db2h, b2d, 4096, 4096);
    bias_comb_kernel<<<2, 256>>>(fcb, nullptr, fcbp, 512, 258);
    pack_cin_kernel<<<640, 256>>>(cin, cinH, cinL);

    // cpre = cin @ cW1i (gate-major plain store)
    hgg(32, 4, cinH, cinL, 320, 320, cW1iT[0], cW1iT[1], 1,
        nullptr, nullptr, 0, cpre, 4096, 4096, nullptr, nullptr, nullptr, 0, nullptr, nullptr, nullptr);
    // conductor h1 init into hcc buf0 cols [0,1024)
    { dim3 g(8, 4); sgemm_kernel<<<g, 256>>>(512, 1024, 512, z, ciW, cib, nullptr, 1, hccH[0], hccL[0], 2048); }

    // conductor: 2 steps
    for (int t = 0; t < 2; t++) {
        int p = t & 1, q = 1 - p;
        hgg(32, 4, hccH[p], hccL[p], 2048, 1024, cW1hT[0], cW1hT[1], 1,
            b1c, cpre, 4096, nullptr, 0, 0, c1c, hccH[q], hccL[q], 2048, nullptr, nullptr, nullptr);
        hgg(32, 4, hccH[q], hccL[q], 2048, 2048, cW2T[0], cW2T[1], 1,
            b2c, nullptr, 0, nullptr, 0, 0, c2c, hccH[p] + 1024, hccL[p] + 1024, 2048,
            nullptr, nullptr, ch + (size_t)t * 512 * 1024);
    }

    // cvec = ch @ coW + cob ; decoder h1 init
    { dim3 g(4, 8); sgemm_kernel<<<g, 256>>>(1024, 512, 1024, ch, coW, cob, cvec, 0, nullptr, nullptr, 0); }
    { dim3 g(8, 8); sgemm_kernel<<<g, 256>>>(1024, 1024, 512, cvec, diW, dib, nullptr, 1, hcH[0], hcL[0], 2048); }

    // decoder input projections
    pack_decin_kernel<<<(unsigned)(((size_t)16384 * 832 + 255) / 256), 256>>>(x, cvec, dinH, dinL);
    hgg(32, 128, dinH, dinL, 832, 832, dW1iT[0], dW1iT[1], 1,
        nullptr, nullptr, 0, dpre, 4096, 4096, nullptr, nullptr, nullptr, 0, nullptr, nullptr, nullptr);

    // decoder recurrence: 16 steps, rows = 1024
    for (int s = 0; s < 16; s++) {
        int p = s & 1, q = 1 - p;
        hgg(32, 8, hcH[p], hcL[p], 2048, 1024, dW1hT[0], dW1hT[1], 1,
            b1d, dpre + (size_t)s * 1024 * 4096, 4096, nullptr, 0, 0,
            c1, hcH[q], hcL[q], 2048, nullptr, nullptr, nullptr);
        hgg(32, 8, hcH[q], hcL[q], 2048, 2048, dW2T[0], dW2T[1], 1,
            b2d, nullptr, 0, nullptr, 0, 0,
            c2, hcH[p] + 1024, hcL[p] + 1024, 2048,
            hsH + (size_t)s * 1024 * 1024, hsL + (size_t)s * 1024 * 1024, nullptr);
    }

    // output head + log_softmax
    hgg(3, 128, hsH, hsL, 1024, 1024, fcWT[0], fcWT[1], 0,
        fcbp, nullptr, 0, logb, 258, 258, nullptr, nullptr, nullptr, 0, nullptr, nullptr, nullptr);
    logsoftmax_kernel<<<16384, 256>>>(logb, out);
}

// round 7
// speedup vs baseline: 2.7924x; 1.0266x over previous
#include <cuda_runtime.h>
#include <cuda_bf16.h>
#include <math.h>
#include <stdint.h>

typedef __nv_bfloat16 bf16;

// ----------------------------- PTX helpers --------------------------------
__device__ __forceinline__ uint32_t smem_u32(const void* p) {
    uint32_t a;
    asm("{ .reg .u64 t; cvta.to.shared.u64 t, %1; cvt.u32.u64 %0, t; }" : "=r"(a) : "l"(p));
    return a;
}
__device__ __forceinline__ void cp16(uint32_t d, const void* s) {
    asm volatile("cp.async.cg.shared.global [%0], [%1], 16;" :: "r"(d), "l"(s) : "memory");
}
#define CP_COMMIT() asm volatile("cp.async.commit_group;" ::: "memory")
#define CP_WAIT0()  asm volatile("cp.async.wait_group 0;" ::: "memory")
#define CP_WAIT1()  asm volatile("cp.async.wait_group 1;" ::: "memory")

__device__ __forceinline__ void ldsm4(uint32_t* r, uint32_t addr) {
    asm volatile("ldmatrix.sync.aligned.m8n8.x4.shared.b16 {%0,%1,%2,%3}, [%4];"
                 : "=r"(r[0]), "=r"(r[1]), "=r"(r[2]), "=r"(r[3]) : "r"(addr));
}
__device__ __forceinline__ void mma_bf16(float* c, const uint32_t* a, const uint32_t* b) {
    asm volatile(
        "mma.sync.aligned.m16n8k16.row.col.f32.bf16.bf16.f32 "
        "{%0,%1,%2,%3}, {%4,%5,%6,%7}, {%8,%9}, {%0,%1,%2,%3};"
        : "+f"(c[0]), "+f"(c[1]), "+f"(c[2]), "+f"(c[3])
        : "r"(a[0]), "r"(a[1]), "r"(a[2]), "r"(a[3]), "r"(b[0]), "r"(b[1]));
}
__device__ __forceinline__ float sigm(float x) { return 1.f / (1.f + expf(-x)); }

// ----------------------------- scratch ------------------------------------
#define DA __device__ __align__(128)
DA float g_dpre[(size_t)16384 * 4096];
DA float g_cpre[(size_t)512 * 4096];
DA float g_cvec[1024 * 512];
DA float g_ch[(size_t)1024 * 1024];
DA float g_c1[1024 * 1024], g_c2[1024 * 1024], g_c1c[512 * 1024], g_c2c[512 * 1024];
DA float g_logb[(size_t)16384 * 258];
DA bf16 g_hc_hi[2][(size_t)1024 * 2048], g_hc_lo[2][(size_t)1024 * 2048];   // decoder concat [h1|h2]
DA bf16 g_hcc_hi[2][(size_t)512 * 2048], g_hcc_lo[2][(size_t)512 * 2048];   // conductor concat
DA bf16 g_hs_hi[(size_t)16384 * 1024], g_hs_lo[(size_t)16384 * 1024];
DA bf16 g_din_hi[(size_t)16384 * 832], g_din_lo[(size_t)16384 * 832];
DA bf16 g_cin_hi[512 * 320], g_cin_lo[512 * 320];
DA bf16 g_cW1h_t[2][(size_t)4096 * 1024], g_cW2_t[2][(size_t)4096 * 2048], g_cW1i_t[2][(size_t)4096 * 320];
DA bf16 g_dW1h_t[2][(size_t)4096 * 1024], g_dW2_t[2][(size_t)4096 * 2048], g_dW1i_t[2][(size_t)4096 * 832];
DA bf16 g_fcW_t[2][(size_t)512 * 1024];
DA float g_b1c[4096], g_b2c[4096], g_b1d[4096], g_b2d[4096], g_fcbp[512];

// ----------------- mma.sync GEMM, 128x128 tile, BK=64 ----------------------
// C = Ahi@Bhi + Ahi@Blo + Alo@Bhi over K (mult of 64); B stored [Nrows,K].
// perm=1: tile col r -> weight row (r>>5)*1024 + nt*32 + (r&31)  (gate-major
//         blocks of 32 units per tile; gate = bits 5..6 of tile col).
// Epilogue: Cst!=0 -> plain fp32 store; else fused LSTM cell (gate-major
// bias/Cadd indexed [g*1024+u]).
// 3-stage cp.async pipeline + kk-level ldmatrix double buffering.
static constexpr int HG_SMEM = 3 * 65536;

__global__ __launch_bounds__(256, 1)
void hgemm(const bf16* __restrict__ Ahi, const bf16* __restrict__ Alo, int lda, int K,
           const bf16* __restrict__ Bhi, const bf16* __restrict__ Blo, int perm,
           const float* __restrict__ bias, const float* __restrict__ Cadd, int ldc,
           float* __restrict__ Cst, int Nlog, int ldcp,
           float* __restrict__ cstate,
           bf16* __restrict__ Hhi, bf16* __restrict__ Hlo, int ldh,
           bf16* __restrict__ H2hi, bf16* __restrict__ H2lo,
           float* __restrict__ Hf)
{
    extern __shared__ char smem_raw[];
    const uint32_t sb = smem_u32(smem_raw);
    const int tid = threadIdx.x, nt = blockIdx.x, m0 = blockIdx.y * 128;
    const int wid = tid >> 5, lane = tid & 31;
    const int wm = wid & 1, wn = wid >> 1;

    int brow[4];
#pragma unroll
    for (int i = 0; i < 4; i++) {
        int r = (tid + i * 256) >> 3;
        brow[i] = perm ? ((r >> 5) * 1024 + nt * 32 + (r & 31)) : (nt * 128 + r);
    }
    const int nk = K >> 6;

    auto load_stage = [&](int st, int k0) {
        const uint32_t base = sb + st * 65536;
#pragma unroll
        for (int i = 0; i < 4; i++) {
            int c = tid + i * 256, row = c >> 3, ch = c & 7;
            uint32_t so = (uint32_t)((row << 7) + ((ch ^ (row & 7)) << 4));
            size_t gA = (size_t)(m0 + row) * lda + k0 + ch * 8;
            cp16(base + so,         Ahi + gA);
            cp16(base + 16384 + so, Alo + gA);
            size_t gB = (size_t)brow[i] * K + k0 + ch * 8;
            cp16(base + 32768 + so, Bhi + gB);
            cp16(base + 49152 + so, Blo + gB);
        }
        CP_COMMIT();
    };

    float acc[4][4][4];
#pragma unroll
    for (int a = 0; a < 4; a++)
#pragma unroll
        for (int b = 0; b < 4; b++)
#pragma unroll
            for (int c = 0; c < 4; c++) acc[a][b][c] = 0.f;

    // per-lane ldmatrix address components
    const int lrowA = (lane & 7) + (((lane >> 3) & 1) << 3);
    const int kselA = lane >> 4;
    const int jselB = lane >> 4;
    const int kselB = (lane >> 3) & 1;
    const int nrB   = lane & 7;

    // fragment buffers (double-buffered over kk)
    uint32_t a_hi[2][4][4], a_lo[2][4][4], b_hi[2][4][2], b_lo[2][4][2];

    auto load_frags = [&](uint32_t base, int kk, int buf) {
#pragma unroll
        for (int mi = 0; mi < 4; mi++) {
            int r = wm * 64 + mi * 16 + lrowA;
            int ch = 2 * kk + kselA;
            uint32_t ad = base + (uint32_t)((r << 7) + ((ch ^ (r & 7)) << 4));
            ldsm4(a_hi[buf][mi], ad);
            ldsm4(a_lo[buf][mi], ad + 16384);
        }
#pragma unroll
        for (int jp = 0; jp < 2; jp++) {
            int j = 2 * jp + jselB;
            int nr = (wn + 4 * j) * 8 + nrB;
            int ch = 2 * kk + kselB;
            uint32_t ad = base + 32768 + (uint32_t)((nr << 7) + ((ch ^ (nr & 7)) << 4));
            ldsm4(&b_hi[buf][2 * jp][0], ad);
            ldsm4(&b_lo[buf][2 * jp][0], ad + 16384);
        }
    };

    // prologue: stages 0 and 1 in flight
    load_stage(0, 0);
    if (nk > 1) load_stage(1, 64);

    for (int i = 0; i < nk; i++) {
        const int st = i % 3;
        if (i + 1 < nk) CP_WAIT1(); else CP_WAIT0();
        __syncthreads();
        if (i + 2 < nk) load_stage((i + 2) % 3, (i + 2) << 6);

        const uint32_t base = sb + st * 65536;
        load_frags(base, 0, 0);
#pragma unroll
        for (int kk = 0; kk < 4; kk++) {
            const int cur = kk & 1;
            if (kk < 3) load_frags(base, kk + 1, cur ^ 1);
#pragma unroll
            for (int mi = 0; mi < 4; mi++)
#pragma unroll
                for (int j = 0; j < 4; j++) {
                    mma_bf16(acc[mi][j], a_hi[cur][mi], b_hi[cur][j]);
                    mma_bf16(acc[mi][j], a_hi[cur][mi], b_lo[cur][j]);
                    mma_bf16(acc[mi][j], a_lo[cur][mi], b_hi[cur][j]);
                }
        }
    }

    // ------------------------------ epilogue -------------------------------
    const int qr = lane >> 2, qc = (lane & 3) * 2;
#pragma unroll
    for (int mi = 0; mi < 4; mi++)
#pragma unroll
        for (int half = 0; half < 2; half++) {
            const int row = m0 + wm * 64 + mi * 16 + qr + half * 8;
            if (Cst) {
#pragma unroll
                for (int j = 0; j < 4; j++)
#pragma unroll
                    for (int ci = 0; ci < 2; ci++) {
                        float v = acc[mi][j][half * 2 + ci];
                        if (perm) {
                            int pst = j * 1024 + nt * 32 + wn * 8 + qc + ci;
                            Cst[(size_t)row * ldcp + pst] = v;
                        } else {
                            int p = nt * 128 + j * 32 + wn * 8 + qc + ci;
                            if (p < Nlog) {
                                if (bias) v += bias[p];
                                Cst[(size_t)row * ldcp + p] = v;
                            }
                        }
                    }
            } else {
                const int u0 = nt * 32 + wn * 8 + qc;
                float2 cold = *(const float2*)&cstate[(size_t)row * 1024 + u0];
                float hv[2];
#pragma unroll
                for (int ci = 0; ci < 2; ci++) {
                    const int u = u0 + ci;
                    float gi = acc[mi][0][half * 2 + ci] + bias[u];
                    float gf = acc[mi][1][half * 2 + ci] + bias[1024 + u];
                    float gg = acc[mi][2][half * 2 + ci] + bias[2048 + u];
                    float go = acc[mi][3][half * 2 + ci] + bias[3072 + u];
                    if (Cadd) {
                        const float* ca = Cadd + (size_t)row * ldc;
                        gi += ca[u]; gf += ca[1024 + u];
                        gg += ca[2048 + u]; go += ca[3072 + u];
                    }
                    float cold_v = ci ? cold.y : cold.x;
                    float cn = sigm(gf) * cold_v + sigm(gi) * tanhf(gg);
                    hv[ci] = sigm(go) * tanhf(cn);
                    if (ci) cold.y = cn; else cold.x = cn;
                }
                *(float2*)&cstate[(size_t)row * 1024 + u0] = cold;
                bf16 h0 = __float2bfloat16(hv[0]), h1 = __float2bfloat16(hv[1]);
                bf16 l0 = __float2bfloat16(hv[0] - __bfloat162float(h0));
                bf16 l1 = __float2bfloat16(hv[1] - __bfloat162float(h1));
                uint32_t hp = (uint32_t)__bfloat16_as_ushort(h0) |
                              ((uint32_t)__bfloat16_as_ushort(h1) << 16);
                uint32_t lp = (uint32_t)__bfloat16_as_ushort(l0) |
                              ((uint32_t)__bfloat16_as_ushort(l1) << 16);
                *(uint32_t*)&Hhi[(size_t)row * ldh + u0] = hp;
                *(uint32_t*)&Hlo[(size_t)row * ldh + u0] = lp;
                if (H2hi) {
                    *(uint32_t*)&H2hi[(size_t)row * 1024 + u0] = hp;
                    *(uint32_t*)&H2lo[(size_t)row * 1024 + u0] = lp;
                }
                if (Hf) {
                    Hf[(size_t)row * 1024 + u0]     = hv[0];
                    Hf[(size_t)row * 1024 + u0 + 1] = hv[1];
                }
            }
        }
}

// ------------------------- small SIMT SGEMM --------------------------------
__global__ __launch_bounds__(256, 2)
void sgemm_kernel(int M, int N, int K, const float* __restrict__ A, const float* __restrict__ B,
                  const float* __restrict__ bias, float* __restrict__ C, int act,
                  bf16* __restrict__ ohi, bf16* __restrict__ olo, int ldo)
{
    __shared__ __align__(16) float As[16][132], Bs[16][128];
    const int tid = threadIdx.x, tc = tid & 15, tr = tid >> 4;
    const int rb = blockIdx.y * 128, cb = blockIdx.x * 128;
    float acc[8][8];
#pragma unroll
    for (int i = 0; i < 8; i++)
#pragma unroll
        for (int j = 0; j < 8; j++) acc[i][j] = 0.f;
    for (int k0 = 0; k0 < K; k0 += 16) {
#pragma unroll
        for (int l = 0; l < 8; l++) {
            int i = tid + l * 256, m = i >> 4, kk = i & 15;
            int gm = rb + m, gk = k0 + kk;
            As[kk][m] = (gm < M && gk < K) ? A[(size_t)gm * K + gk] : 0.f;
        }
#pragma unroll
        for (int l = 0; l < 8; l++) {
            int i = tid + l * 256, kk = i >> 7, n = i & 127;
            int gk = k0 + kk, gn = cb + n;
            Bs[kk][n] = (gk < K && gn < N) ? B[(size_t)gk * N + gn] : 0.f;
        }
        __syncthreads();
#pragma unroll
        for (int kk = 0; kk < 16; kk++) {
            float a[8], b[8];
            *(float4*)&a[0] = *(const float4*)&As[kk][tr * 8];
            *(float4*)&a[4] = *(const float4*)&As[kk][tr * 8 + 4];
            *(float4*)&b[0] = *(const float4*)&Bs[kk][tc * 8];
            *(float4*)&b[4] = *(const float4*)&Bs[kk][tc * 8 + 4];
#pragma unroll
            for (int i = 0; i < 8; i++)
#pragma unroll
                for (int j = 0; j < 8; j++) acc[i][j] = fmaf(a[i], b[j], acc[i][j]);
        }
        __syncthreads();
    }
#pragma unroll
    for (int i = 0; i < 8; i++) {
        int gm = rb + tr * 8 + i;
        if (gm >= M) continue;
#pragma unroll
        for (int j = 0; j < 8; j++) {
            int gn = cb + tc * 8 + j;
            if (gn >= N) continue;
            float v = acc[i][j];
            if (bias) v += bias[gn];
            if (act) v = tanhf(v);
            if (C) C[(size_t)gm * N + gn] = v;
            if (ohi) {
                bf16 h = __float2bfloat16(v);
                ohi[(size_t)gm * ldo + gn] = h;
                olo[(size_t)gm * ldo + gn] = __float2bfloat16(v - __bfloat162float(h));
            }
        }
    }
}

// -------------------- transpose + bf16 split, zero-padded -------------------
__global__ void tsplit_kernel(const float* __restrict__ src, bf16* __restrict__ dhi,
                              bf16* __restrict__ dlo, int Ksrc, int Nsrc,
                              int src_ld, int ldd, int col0)
{
    __shared__ float t[32][33];
    const int k0 = blockIdx.x * 32, n0 = blockIdx.y * 32;
#pragma unroll
    for (int y = 0; y < 4; y++) {
        int k = k0 + threadIdx.y + y * 8, n = n0 + threadIdx.x;
        t[threadIdx.y + y * 8][threadIdx.x] = (k < Ksrc && n < Nsrc) ? src[(size_t)k * src_ld + n] : 0.f;
    }
    __syncthreads();
#pragma unroll
    for (int y = 0; y < 4; y++) {
        int n = n0 + threadIdx.y + y * 8, k = k0 + threadIdx.x;
        float w = t[threadIdx.x][threadIdx.y + y * 8];
        bf16 h = __float2bfloat16(w);
        dhi[(size_t)n * ldd + col0 + k] = h;
        dlo[(size_t)n * ldd + col0 + k] = __float2bfloat16(w - __bfloat162float(h));
    }
}

__global__ void bias_comb_kernel(const float* __restrict__ b0, const float* __restrict__ b1,
                                 float* __restrict__ out, int n_out, int n_src)
{
    int p = blockIdx.x * blockDim.x + threadIdx.x;
    if (p >= n_out) return;
    float v = 0.f;
    if (p < n_src) { v = b0[p]; if (b1) v += b1[p]; }
    out[p] = v;
}

__global__ void pack_cin_kernel(const float* __restrict__ cin, bf16* dhi, bf16* dlo)
{
    int idx = blockIdx.x * blockDim.x + threadIdx.x;
    if (idx >= 512 * 320) return;
    int b = idx / 320, v = idx - b * 320;
    float x = (v < 258) ? cin[(size_t)b * 258 + v] : 0.f;
    bf16 h = __float2bfloat16(x);
    dhi[idx] = h; dlo[idx] = __float2bfloat16(x - __bfloat162float(h));
}

__global__ void pack_decin_kernel(const float* __restrict__ x, const float* __restrict__ c,
                                  bf16* dhi, bf16* dlo)
{
    size_t idx = (size_t)blockIdx.x * blockDim.x + threadIdx.x;
    if (idx >= (size_t)16384 * 832) return;
    int col = (int)(idx % 832), r = (int)(idx / 832);
    int b = r & 511, u = (r >> 9) & 1, s = r >> 10;
    float v = 0.f;
    if (col < 512) v = c[(size_t)(u * 512 + b) * 512 + col];
    else if (col < 770) {
        int vv = col - 512, t = u * 16 + s;
        v = (t == 0) ? (vv == 0 ? 1.f : 0.f) : x[((size_t)(t - 1) * 512 + b) * 258 + vv];
    }
    bf16 h = __float2bfloat16(v);
    dhi[idx] = h; dlo[idx] = __float2bfloat16(v - __bfloat162float(h));
}

// warp-per-row log_softmax; row r = s*1024 + u*512 + b -> out[b, u*16+s, :]
__global__ void logsoftmax_kernel(const float* __restrict__ logits, float* __restrict__ out)
{
    int w = (blockIdx.x * blockDim.x + threadIdx.x) >> 5;
    int lane = threadIdx.x & 31;
    if (w >= 16384) return;
    const float* row = logits + (size_t)w * 258;
    float lm = -1e30f;
    for (int v = lane; v < 258; v += 32) lm = fmaxf(lm, row[v]);
#pragma unroll
    for (int o = 16; o; o >>= 1) lm = fmaxf(lm, __shfl_xor_sync(0xFFFFFFFFu, lm, o));
    float ls = 0.f;
    for (int v = lane; v < 258; v += 32) ls += expf(row[v] - lm);
#pragma unroll
    for (int o = 16; o; o >>= 1) ls += __shfl_xor_sync(0xFFFFFFFFu, ls, o);
    float lse = lm + logf(ls);
    int b = w & 511, u = (w >> 9) & 1, s = w >> 10;
    float* o = out + ((size_t)b * 32 + (u * 16 + s)) * 258;
    for (int v = lane; v < 258; v += 32) o[v] = row[v] - lse;
}

// ------------------------------- host --------------------------------------
static void hgg(int Ngrid, int Mtiles, const bf16* Ahi, const bf16* Alo, int lda, int K,
                const bf16* Bhi, const bf16* Blo, int perm,
                const float* bias, const float* Cadd, int ldc,
                float* Cst, int Nlog, int ldcp, float* cs,
                bf16* Hhi, bf16* Hlo, int ldh, bf16* H2hi, bf16* H2lo, float* Hf)
{
    dim3 g(Ngrid, Mtiles);
    hgemm<<<g, 256, HG_SMEM>>>(Ahi, Alo, lda, K, Bhi, Blo, perm, bias, Cadd, ldc,
                               Cst, Nlog, ldcp, cs, Hhi, Hlo, ldh, H2hi, H2lo, Hf);
}
static void tsp(const float* src, bf16* dhi, bf16* dlo, int Ksrc, int Nsrc,
                int src_ld, int Kpad, int Npad, int ldd, int col0)
{
    dim3 g(Kpad / 32, Npad / 32), b(32, 8);
    tsplit_kernel<<<g, b>>>(src, dhi, dlo, Ksrc, Nsrc, src_ld, ldd, col0);
}
#define GS(p, s) cudaGetSymbolAddress((void**)&p, s)

extern "C" void kernel_launch(void* const* d_in, const int* in_sizes, int n_in,
                              void* d_out, int out_size)
{
    const float *z = (const float*)d_in[0], *x = (const float*)d_in[1], *cin = (const float*)d_in[2];
    const float *ciW = (const float*)d_in[3], *cib = (const float*)d_in[4];
    const float *cW1i = (const float*)d_in[5], *cW1h = (const float*)d_in[6];
    const float *cb1i = (const float*)d_in[7], *cb1h = (const float*)d_in[8];
    const float *cW2i = (const float*)d_in[9], *cW2h = (const float*)d_in[10];
    const float *cb2i = (const float*)d_in[11], *cb2h = (const float*)d_in[12];
    const float *coW = (const float*)d_in[13], *cob = (const float*)d_in[14];
    const float *diW = (const float*)d_in[15], *dib = (const float*)d_in[16];
    const float *dW1i = (const float*)d_in[17], *dW1h = (const float*)d_in[18];
    const float *db1i = (const float*)d_in[19], *db1h = (const float*)d_in[20];
    const float *dW2i = (const float*)d_in[21], *dW2h = (const float*)d_in[22];
    const float *db2i = (const float*)d_in[23], *db2h = (const float*)d_in[24];
    const float *fcW = (const float*)d_in[25], *fcb = (const float*)d_in[26];
    float* out = (float*)d_out;

    cudaFuncSetAttribute(hgemm, cudaFuncAttributeMaxDynamicSharedMemorySize, HG_SMEM);

    float *dpre, *cpre, *cvec, *ch, *c1, *c2, *c1c, *c2c, *logb;
    float *b1c, *b2c, *b1d, *b2d, *fcbp;
    bf16 *hcH[2], *hcL[2], *hccH[2], *hccL[2], *hsH, *hsL, *dinH, *dinL, *cinH, *cinL;
    bf16 *cW1hT[2], *cW2T[2], *cW1iT[2], *dW1hT[2], *dW2T[2], *dW1iT[2], *fcWT[2];
    GS(dpre, g_dpre); GS(cpre, g_cpre); GS(cvec, g_cvec); GS(ch, g_ch);
    GS(c1, g_c1); GS(c2, g_c2); GS(c1c, g_c1c); GS(c2c, g_c2c); GS(logb, g_logb);
    GS(b1c, g_b1c); GS(b2c, g_b2c); GS(b1d, g_b1d); GS(b2d, g_b2d); GS(fcbp, g_fcbp);
    { bf16* p; GS(p, g_hc_hi); hcH[0] = p; hcH[1] = p + (size_t)1024 * 2048; }
    { bf16* p; GS(p, g_hc_lo); hcL[0] = p; hcL[1] = p + (size_t)1024 * 2048; }
    { bf16* p; GS(p, g_hcc_hi); hccH[0] = p; hccH[1] = p + (size_t)512 * 2048; }
    { bf16* p; GS(p, g_hcc_lo); hccL[0] = p; hccL[1] = p + (size_t)512 * 2048; }
    GS(hsH, g_hs_hi); GS(hsL, g_hs_lo); GS(dinH, g_din_hi); GS(dinL, g_din_lo);
    GS(cinH, g_cin_hi); GS(cinL, g_cin_lo);
    { bf16* p; GS(p, g_cW1h_t); cW1hT[0] = p; cW1hT[1] = p + (size_t)4096 * 1024; }
    { bf16* p; GS(p, g_cW2_t);  cW2T[0] = p;  cW2T[1] = p + (size_t)4096 * 2048; }
    { bf16* p; GS(p, g_cW1i_t); cW1iT[0] = p; cW1iT[1] = p + (size_t)4096 * 320; }
    { bf16* p; GS(p, g_dW1h_t); dW1hT[0] = p; dW1hT[1] = p + (size_t)4096 * 1024; }
    { bf16* p; GS(p, g_dW2_t);  dW2T[0] = p;  dW2T[1] = p + (size_t)4096 * 2048; }
    { bf16* p; GS(p, g_dW1i_t); dW1iT[0] = p; dW1iT[1] = p + (size_t)4096 * 832; }
    { bf16* p; GS(p, g_fcW_t);  fcWT[0] = p;  fcWT[1] = p + (size_t)512 * 1024; }

    // zero init: ping-pong buffer 1 (h2 region read at step 0) + cell states
    cudaMemsetAsync(hcH[1], 0, (size_t)1024 * 2048 * 2);
    cudaMemsetAsync(hcL[1], 0, (size_t)1024 * 2048 * 2);
    cudaMemsetAsync(hccH[1], 0, (size_t)512 * 2048 * 2);
    cudaMemsetAsync(hccL[1], 0, (size_t)512 * 2048 * 2);
    cudaMemsetAsync(c1, 0, (size_t)1024 * 1024 * 4);
    cudaMemsetAsync(c2, 0, (size_t)1024 * 1024 * 4);
    cudaMemsetAsync(c1c, 0, (size_t)512 * 1024 * 4);
    cudaMemsetAsync(c2c, 0, (size_t)512 * 1024 * 4);

    // weight prep (transpose + hi/lo split; zero-padded)
    tsp(cW1h, cW1hT[0], cW1hT[1], 1024, 4096, 4096, 1024, 4096, 1024, 0);
    tsp(cW2i, cW2T[0], cW2T[1], 1024, 4096, 4096, 1024, 4096, 2048, 0);
    tsp(cW2h, cW2T[0], cW2T[1], 1024, 4096, 4096, 1024, 4096, 2048, 1024);
    tsp(cW1i, cW1iT[0], cW1iT[1], 258, 4096, 4096, 320, 4096, 320, 0);
    tsp(dW1h, dW1hT[0], dW1hT[1], 1024, 4096, 4096, 1024, 4096, 1024, 0);
    tsp(dW2i, dW2T[0], dW2T[1], 1024, 4096, 4096, 1024, 4096, 2048, 0);
    tsp(dW2h, dW2T[0], dW2T[1], 1024, 4096, 4096, 1024, 4096, 2048, 1024);
    tsp(dW1i, dW1iT[0], dW1iT[1], 770, 4096, 4096, 832, 4096, 832, 0);
    tsp(fcW, fcWT[0], fcWT[1], 1024, 258, 258, 1024, 512, 1024, 0);
    bias_comb_kernel<<<16, 256>>>(cb1i, cb1h, b1c, 4096, 4096);
    bias_comb_kernel<<<16, 256>>>(cb2i, cb2h, b2c, 4096, 4096);
    bias_comb_kernel<<<16, 256>>>(db1i, db1h, b1d, 4096, 4096);
    bias_comb_kernel<<<16, 256>>>(db2i, db2h, b2d, 4096, 4096);
    bias_comb_kernel<<<2, 256>>>(fcb, nullptr, fcbp, 512, 258);
    pack_cin_kernel<<<640, 256>>>(cin, cinH, cinL);

    // cpre = cin @ cW1i (gate-major plain store)
    hgg(32, 4, cinH, cinL, 320, 320, cW1iT[0], cW1iT[1], 1,
        nullptr, nullptr, 0, cpre, 4096, 4096, nullptr, nullptr, nullptr, 0, nullptr, nullptr, nullptr);
    // conductor h1 init into hcc buf0 cols [0,1024)
    { dim3 g(8, 4); sgemm_kernel<<<g, 256>>>(512, 1024, 512, z, ciW, cib, nullptr, 1, hccH[0], hccL[0], 2048); }

    // conductor: 2 steps
    for (int t = 0; t < 2; t++) {
        int p = t & 1, q = 1 - p;
        hgg(32, 4, hccH[p], hccL[p], 2048, 1024, cW1hT[0], cW1hT[1], 1,
            b1c, cpre, 4096, nullptr, 0, 0, c1c, hccH[q], hccL[q], 2048, nullptr, nullptr, nullptr);
        hgg(32, 4, hccH[q], hccL[q], 2048, 2048, cW2T[0], cW2T[1], 1,
            b2c, nullptr, 0, nullptr, 0, 0, c2c, hccH[p] + 1024, hccL[p] + 1024, 2048,
            nullptr, nullptr, ch + (size_t)t * 512 * 1024);
    }

    // cvec = ch @ coW + cob ; decoder h1 init
    { dim3 g(4, 8); sgemm_kernel<<<g, 256>>>(1024, 512, 1024, ch, coW, cob, cvec, 0, nullptr, nullptr, 0); }
    { dim3 g(8, 8); sgemm_kernel<<<g, 256>>>(1024, 1024, 512, cvec, diW, dib, nullptr, 1, hcH[0], hcL[0], 2048); }

    // decoder input projections
    pack_decin_kernel<<<(unsigned)(((size_t)16384 * 832 + 255) / 256), 256>>>(x, cvec, dinH, dinL);
    hgg(32, 128, dinH, dinL, 832, 832, dW1iT[0], dW1iT[1], 1,
        nullptr, nullptr, 0, dpre, 4096, 4096, nullptr, nullptr, nullptr, 0, nullptr, nullptr, nullptr);

    // decoder recurrence: 16 steps, rows = 1024
    for (int s = 0; s < 16; s++) {
        int p = s & 1, q = 1 - p;
        hgg(32, 8, hcH[p], hcL[p], 2048, 1024, dW1hT[0], dW1hT[1], 1,
            b1d, dpre + (size_t)s * 1024 * 4096, 4096, nullptr, 0, 0,
            c1, hcH[q], hcL[q], 2048, nullptr, nullptr, nullptr);
        hgg(32, 8, hcH[q], hcL[q], 2048, 2048, dW2T[0], dW2T[1], 1,
            b2d, nullptr, 0, nullptr, 0, 0,
            c2, hcH[p] + 1024, hcL[p] + 1024, 2048,
            hsH + (size_t)s * 1024 * 1024, hsL + (size_t)s * 1024 * 1024, nullptr);
    }

    // output head + log_softmax
    hgg(3, 128, hsH, hsL, 1024, 1024, fcWT[0], fcWT[1], 0,
        fcbp, nullptr, 0, logb, 258, 258, nullptr, nullptr, nullptr, 0, nullptr, nullptr, nullptr);
    logsoftmax_kernel<<<2048, 256>>>(logb, out);
}